// round 6
// baseline (speedup 1.0000x reference)
#include <cuda_runtime.h>
#include <cuda_bf16.h>
#include <mma.h>
#include <cstdint>

#define N_NODES 100000
#define E_EDGES 400000
#define DN 64
#define DE 32
#define DH 64
#define DIN_E 160
#define DIN_N 128
#define TN 64
#define NT 256
#define NB ((N_NODES + TN - 1) / TN)    // 1563
#define BSTR 68
#define NSTR 132

#define TE2 128
#define EB2 (E_EDGES / TE2)             // 3125 exact

typedef unsigned long long u64;
using namespace nvcuda;

// Scratch (no cudaMalloc allowed).
// slots: 0 = a<-aa(row), 1 = a<-ab(row), 2 = b<-ab(col), 3 = b<-bb(row)
__device__ float g_sum[4][N_NODES * DE];
__device__ float g_cnt[4][N_NODES];
// Precomputed per-node edge-layer1 partials.
// seg: 0=P0(xa,A0,+b) 1=Q0(xa,B0) 2=P1(xa,A1,+b) 3=Q1(xb,B1) 4=P2(xb,A2,+b) 5=Q2(xb,B2)
__device__ float g_PQ[6][N_NODES * DH];

__global__ void zero_kernel() {
    int idx = blockIdx.x * blockDim.x + threadIdx.x;
    int stride = gridDim.x * blockDim.x;
    float* s = &g_sum[0][0];
    for (int i = idx; i < 4 * N_NODES * DE; i += stride) s[i] = 0.0f;
    float* c = &g_cnt[0][0];
    for (int i = idx; i < 4 * N_NODES; i += stride) c[i] = 0.0f;
}

// ---- packed fp32x2 helpers (for fp32 kernels) ----
__device__ __forceinline__ u64 pack_dup(float x) {
    u64 r; asm("mov.b64 %0, {%1, %1};" : "=l"(r) : "r"(__float_as_uint(x))); return r;
}
__device__ __forceinline__ u64 pack_pair(float x, float y) {
    u64 r; asm("mov.b64 %0, {%1, %2};" : "=l"(r) : "r"(__float_as_uint(x)), "r"(__float_as_uint(y))); return r;
}
__device__ __forceinline__ float2 unpack(u64 v) {
    float2 f; asm("mov.b64 {%0, %1}, %2;" : "=f"(f.x), "=f"(f.y) : "l"(v)); return f;
}
__device__ __forceinline__ void fma2(u64& acc, u64 a, u64 b) {
    asm("fma.rn.f32x2 %0, %1, %2, %0;" : "+l"(acc) : "l"(a), "l"(b));
}

template <int KW, int STR>
__device__ __forceinline__ void accum_l1(
    const float* buf, const float* __restrict__ W, int te, int th, u64 acc[4][2])
{
    const float* row = buf + (te * 4) * STR;
    #pragma unroll 4
    for (int k = 0; k < KW; k += 4) {
        float4 a0 = *(const float4*)(row + 0 * STR + k);
        float4 a1 = *(const float4*)(row + 1 * STR + k);
        float4 a2 = *(const float4*)(row + 2 * STR + k);
        float4 a3 = *(const float4*)(row + 3 * STR + k);
        const float* a[4] = {(const float*)&a0, (const float*)&a1,
                             (const float*)&a2, (const float*)&a3};
        #pragma unroll
        for (int kk = 0; kk < 4; kk++) {
            ulonglong2 wp = *((const ulonglong2*)(W + (k + kk) * DH) + th);
            #pragma unroll
            for (int i = 0; i < 4; i++) {
                u64 xx = pack_dup(a[i][kk]);
                fma2(acc[i][0], xx, wp.x);
                fma2(acc[i][1], xx, wp.y);
            }
        }
    }
}

// ---------------------------------------------------------------------------
// Precompute kernel: 6 dense GEMMs  g_PQ[seg] = x @ Wblk (+bias for P segs).
// ---------------------------------------------------------------------------
__global__ void __launch_bounds__(NT, 4) pre_gemm(
    const float* __restrict__ x_a, const float* __restrict__ x_b,
    const float* __restrict__ We1, const float* __restrict__ be1)
{
    __shared__ float buf[TN * BSTR];

    const int tid = threadIdx.x;
    const int seg = blockIdx.x / NB;
    const int rblk = blockIdx.x - seg * NB;
    const int r0 = rblk * TN;

    const int type = seg >> 1;
    const int part = seg & 1;
    const float* x = (seg <= 2) ? x_a : x_b;
    const float* W = We1 + type * DIN_E * DH + part * 64 * DH;
    float* outp = g_PQ[seg];

    for (int it = tid; it < TN * 16; it += NT) {
        int n = it >> 4, c = it & 15;
        int gn = r0 + n; if (gn >= N_NODES) gn = N_NODES - 1;
        *(float4*)(buf + n * BSTR + c * 4) =
            __ldg((const float4*)(x + (size_t)gn * DN) + c);
    }
    __syncthreads();

    const int th = tid & 15;
    const int te = tid >> 4;

    u64 acc[4][2];
    if (part == 0) {
        float4 bv = __ldg((const float4*)(be1 + type * DH) + th);
        u64 p0 = pack_pair(bv.x, bv.y);
        u64 p1 = pack_pair(bv.z, bv.w);
        #pragma unroll
        for (int i = 0; i < 4; i++) { acc[i][0] = p0; acc[i][1] = p1; }
    } else {
        #pragma unroll
        for (int i = 0; i < 4; i++) { acc[i][0] = 0ull; acc[i][1] = 0ull; }
    }

    accum_l1<64, BSTR>(buf, W, te, th, acc);

    #pragma unroll
    for (int i = 0; i < 4; i++) {
        int gn = r0 + te * 4 + i;
        if (gn < N_NODES) {
            float2 o0 = unpack(acc[i][0]);
            float2 o1 = unpack(acc[i][1]);
            float4 ov; ov.x = o0.x; ov.y = o0.y; ov.z = o1.x; ov.w = o1.y;
            *(float4*)(outp + (size_t)gn * DH + th * 4) = ov;
        }
    }
}

// ===========================================================================
// wmma (HMMA bf16, 3-term split) edge kernel — portable to compute_103 PTX.
// ===========================================================================

// byte offsets into dynamic smem
#define OA    0            // Ahi [128][40]bf16 @0, Alo @10240; reused: Hhi [128][72]bf16
#define OALO  10240
#define OB1H  20480        // B1hi [32][72]bf16
#define OB1L  25088
#define OW2H  29696        // W2hi [64][40]bf16
#define OW2L  34816
#define OHLO  39936        // Hlo [128][72]bf16
#define OD1   58368        // D1 [128][72]f32 ; reused: D2 [128][36]f32
#define OIDX  95232        // src[128], dst[128]
#define ESMEM 96256

#define ASTRIDE 40
#define B1STRIDE 72
#define W2STRIDE 40
#define HSTRIDE 72
#define D1STRIDE 72
#define D2STRIDE 36

// split x,y into bf16x2 hi + bf16x2 lo words
__device__ __forceinline__ void split2(float x, float y, uint32_t& hi, uint32_t& lo) {
    __nv_bfloat162 h2 = __float22bfloat162_rn(make_float2(x, y));
    float2 hb = __bfloat1622float2(h2);
    __nv_bfloat162 l2 = __float22bfloat162_rn(make_float2(x - hb.x, y - hb.y));
    hi = *(uint32_t*)&h2;
    lo = *(uint32_t*)&l2;
}

typedef wmma::fragment<wmma::matrix_a, 16, 16, 16, __nv_bfloat16, wmma::row_major> FragA;
typedef wmma::fragment<wmma::matrix_b, 16, 16, 16, __nv_bfloat16, wmma::row_major> FragB;
typedef wmma::fragment<wmma::accumulator, 16, 16, 16, float> FragC;

__global__ void __launch_bounds__(256) edge_tc(
    const int* __restrict__ ei_aa, const int* __restrict__ ei_ab,
    const int* __restrict__ ei_bb,
    const float* __restrict__ ea_aa, const float* __restrict__ ea_ab,
    const float* __restrict__ ea_bb,
    const float* __restrict__ We1,
    const float* __restrict__ We2, const float* __restrict__ be2,
    float* __restrict__ ne_base)
{
    extern __shared__ __align__(256) char smem[];
    __nv_bfloat16* Ahi = (__nv_bfloat16*)(smem + OA);
    __nv_bfloat16* Alo = (__nv_bfloat16*)(smem + OALO);
    __nv_bfloat16* B1h = (__nv_bfloat16*)(smem + OB1H);
    __nv_bfloat16* B1l = (__nv_bfloat16*)(smem + OB1L);
    __nv_bfloat16* W2h = (__nv_bfloat16*)(smem + OW2H);
    __nv_bfloat16* W2l = (__nv_bfloat16*)(smem + OW2L);
    __nv_bfloat16* Hhi = (__nv_bfloat16*)(smem + OA);     // reuse A region
    __nv_bfloat16* Hlo = (__nv_bfloat16*)(smem + OHLO);
    float* D1 = (float*)(smem + OD1);
    float* D2 = (float*)(smem + OD1);                      // reuse D1 region
    int* sIdx = (int*)(smem + OIDX);                       // [0..127]=src, [128..255]=dst

    const int tid = threadIdx.x;
    const int wid = tid >> 5;

    const int type = blockIdx.x / EB2;
    const int e0 = (blockIdx.x - type * EB2) * TE2;

    const int* ei = (type == 0) ? ei_aa : (type == 1) ? ei_ab : ei_bb;
    const float* ea = (type == 0) ? ea_aa : (type == 1) ? ea_ab : ea_bb;
    const float* C  = We1 + type * DIN_E * DH + 128 * DH;   // [32 x 64] row-major (k x n)
    const float* W2 = We2 + type * DH * DE;                 // [64 x 32] row-major (k x n)
    const float* b2 = be2 + type * DE;
    float* ne = ne_base + (size_t)type * E_EDGES * DE;
    const int slot_row = (type == 0) ? 0 : (type == 1) ? 1 : 3;
    const bool has_col = (type == 1);

    // ---- stage indices ----
    if (tid < 128) sIdx[tid] = __ldg(ei + e0 + tid);
    else sIdx[tid] = __ldg(ei + E_EDGES + e0 + tid - 128);

    // ---- stage A (ea) split: thread -> (row, 16-col half) ----
    {
        int r = tid >> 1, cb = (tid & 1) * 16;
        const float4* earow = (const float4*)(ea + (size_t)(e0 + r) * DE + cb);
        #pragma unroll
        for (int g = 0; g < 4; g++) {
            float4 v = __ldg(earow + g);
            uint32_t h0, l0, h1, l1;
            split2(v.x, v.y, h0, l0);
            split2(v.z, v.w, h1, l1);
            int o = r * ASTRIDE + cb + g * 4;
            *(uint2*)(Ahi + o) = make_uint2(h0, h1);
            *(uint2*)(Alo + o) = make_uint2(l0, l1);
        }
    }
    // ---- stage B1 (C) split ----
    for (int i = tid; i < 32 * 64; i += 256) {
        int k = i >> 6, n = i & 63;
        float v = __ldg(C + i);
        __nv_bfloat16 h = __float2bfloat16_rn(v);
        B1h[k * B1STRIDE + n] = h;
        B1l[k * B1STRIDE + n] = __float2bfloat16_rn(v - __bfloat162float(h));
    }
    // ---- stage W2 split ----
    for (int i = tid; i < 64 * 32; i += 256) {
        int k = i >> 5, n = i & 31;
        float v = __ldg(W2 + i);
        __nv_bfloat16 h = __float2bfloat16_rn(v);
        W2h[k * W2STRIDE + n] = h;
        W2l[k * W2STRIDE + n] = __float2bfloat16_rn(v - __bfloat162float(h));
    }
    __syncthreads();

    // ---- MMA1: D1[128x64] = ea @ C  (hi*hi + hi*lo + lo*hi) ----
    {
        FragA aH[2], aL[2];
        #pragma unroll
        for (int k = 0; k < 2; k++) {
            wmma::load_matrix_sync(aH[k], Ahi + wid * 16 * ASTRIDE + k * 16, ASTRIDE);
            wmma::load_matrix_sync(aL[k], Alo + wid * 16 * ASTRIDE + k * 16, ASTRIDE);
        }
        #pragma unroll
        for (int nt = 0; nt < 4; nt++) {
            FragC acc;
            wmma::fill_fragment(acc, 0.0f);
            #pragma unroll
            for (int k = 0; k < 2; k++) {
                FragB bH, bL;
                wmma::load_matrix_sync(bH, B1h + k * 16 * B1STRIDE + nt * 16, B1STRIDE);
                wmma::load_matrix_sync(bL, B1l + k * 16 * B1STRIDE + nt * 16, B1STRIDE);
                wmma::mma_sync(acc, aH[k], bH, acc);
                wmma::mma_sync(acc, aH[k], bL, acc);
                wmma::mma_sync(acc, aL[k], bH, acc);
            }
            wmma::store_matrix_sync(D1 + wid * 16 * D1STRIDE + nt * 16, acc,
                                    D1STRIDE, wmma::mem_row_major);
        }
    }
    __syncthreads();

    // ---- epilogue 1: h = relu(D1 + P[src] + Q[dst]) -> bf16 split ----
    {
        int r = tid >> 1, cb = (tid & 1) * 32;
        int s = sIdx[r], d = sIdx[128 + r];
        const float4* Pp = (const float4*)(g_PQ[2 * type] + (size_t)s * DH + cb);
        const float4* Qp = (const float4*)(g_PQ[2 * type + 1] + (size_t)d * DH + cb);
        const float* drow = D1 + r * D1STRIDE + cb;
        uint2 hiw[8], low[8];
        #pragma unroll
        for (int g = 0; g < 8; g++) {
            float4 p = __ldg(Pp + g);
            float4 q = __ldg(Qp + g);
            float4 dv = *(const float4*)(drow + g * 4);
            float h0 = fmaxf(dv.x + p.x + q.x, 0.f);
            float h1 = fmaxf(dv.y + p.y + q.y, 0.f);
            float h2 = fmaxf(dv.z + p.z + q.z, 0.f);
            float h3 = fmaxf(dv.w + p.w + q.w, 0.f);
            split2(h0, h1, hiw[g].x, low[g].x);
            split2(h2, h3, hiw[g].y, low[g].y);
        }
        __syncthreads();   // D1 reads done before H overwrites A region / D2 reuse
        #pragma unroll
        for (int g = 0; g < 8; g++) {
            int o = r * HSTRIDE + cb + g * 4;
            *(uint2*)(Hhi + o) = hiw[g];
            *(uint2*)(Hlo + o) = low[g];
        }
    }
    __syncthreads();

    // ---- MMA2: D2[128x32] = h @ W2 ----
    {
        FragA aH[4], aL[4];
        #pragma unroll
        for (int k = 0; k < 4; k++) {
            wmma::load_matrix_sync(aH[k], Hhi + wid * 16 * HSTRIDE + k * 16, HSTRIDE);
            wmma::load_matrix_sync(aL[k], Hlo + wid * 16 * HSTRIDE + k * 16, HSTRIDE);
        }
        #pragma unroll
        for (int nt = 0; nt < 2; nt++) {
            FragC acc;
            wmma::fill_fragment(acc, 0.0f);
            #pragma unroll
            for (int k = 0; k < 4; k++) {
                FragB bH, bL;
                wmma::load_matrix_sync(bH, W2h + k * 16 * W2STRIDE + nt * 16, W2STRIDE);
                wmma::load_matrix_sync(bL, W2l + k * 16 * W2STRIDE + nt * 16, W2STRIDE);
                wmma::mma_sync(acc, aH[k], bH, acc);
                wmma::mma_sync(acc, aH[k], bL, acc);
                wmma::mma_sync(acc, aL[k], bH, acc);
            }
            wmma::store_matrix_sync(D2 + wid * 16 * D2STRIDE + nt * 16, acc,
                                    D2STRIDE, wmma::mem_row_major);
        }
    }
    __syncthreads();

    // ---- epilogue 2: ne = D2 + b2, write + scatter atomics ----
    {
        int r = tid >> 1, cb = (tid & 1) * 16;
        int s = sIdx[r], d = sIdx[128 + r];
        const float* drow = D2 + r * D2STRIDE + cb;
        float* nerow = ne + (size_t)(e0 + r) * DE + cb;
        float v[16];
        #pragma unroll
        for (int g = 0; g < 4; g++) {
            float4 bb = __ldg((const float4*)(b2 + cb) + g);
            float4 dv = *(const float4*)(drow + g * 4);
            float4 o;
            o.x = dv.x + bb.x; o.y = dv.y + bb.y;
            o.z = dv.z + bb.z; o.w = dv.w + bb.w;
            *(float4*)(nerow + g * 4) = o;
            v[g * 4 + 0] = o.x; v[g * 4 + 1] = o.y;
            v[g * 4 + 2] = o.z; v[g * 4 + 3] = o.w;
        }
        float* sum_row = g_sum[slot_row] + (size_t)s * DE + cb;
        #pragma unroll
        for (int j = 0; j < 16; j++) atomicAdd(sum_row + j, v[j]);
        if (has_col) {
            float* sum_col = g_sum[2] + (size_t)d * DE + cb;
            #pragma unroll
            for (int j = 0; j < 16; j++) atomicAdd(sum_col + j, v[j]);
        }
        if ((tid & 1) == 0) {
            atomicAdd(g_cnt[slot_row] + s, 1.0f);
            if (has_col) atomicAdd(g_cnt[2] + d, 1.0f);
        }
    }
}

// ---------------------------------------------------------------------------
// Node kernel (both types merged) — fp32 path.
// ---------------------------------------------------------------------------
__global__ void __launch_bounds__(NT, 4) node_all(
    const float* __restrict__ x_a, const float* __restrict__ x_b,
    const float* __restrict__ Wn1, const float* __restrict__ bn1,
    const float* __restrict__ Wn2, const float* __restrict__ bn2,
    float* __restrict__ out)
{
    __shared__ float buf[TN * NSTR];

    const int tid = threadIdx.x;
    const int type = blockIdx.x / NB;
    const int nblk = blockIdx.x - type * NB;
    const int n0 = nblk * TN;

    const float* x = type ? x_b : x_a;
    const float* sum1 = g_sum[type ? 2 : 0];
    const float* cnt1 = g_cnt[type ? 2 : 0];
    const float* sum2 = g_sum[type ? 3 : 1];
    const float* cnt2 = g_cnt[type ? 3 : 1];
    const float* W1 = Wn1 + type * DIN_N * DH;
    const float* b1 = bn1 + type * DH;
    const float* W2 = Wn2 + type * DH * DN;
    const float* b2 = bn2 + type * DN;
    float* o = out + (size_t)type * N_NODES * DN;

    for (int it = tid; it < TN * 32; it += NT) {
        int n = it >> 5, c4 = it & 31;
        int gn = n0 + n;
        float4 v = make_float4(0.f, 0.f, 0.f, 0.f);
        if (gn < N_NODES) {
            if (c4 < 16) {
                v = __ldg((const float4*)(x + (size_t)gn * DN) + c4);
            } else if (c4 < 24) {
                v = *((const float4*)(sum1 + (size_t)gn * DE) + (c4 - 16));
                float rc = 1.0f / fmaxf(cnt1[gn], 1.0f);
                v.x *= rc; v.y *= rc; v.z *= rc; v.w *= rc;
            } else {
                v = *((const float4*)(sum2 + (size_t)gn * DE) + (c4 - 24));
                float rc = 1.0f / fmaxf(cnt2[gn], 1.0f);
                v.x *= rc; v.y *= rc; v.z *= rc; v.w *= rc;
            }
        }
        *(float4*)(buf + n * NSTR + c4 * 4) = v;
    }
    __syncthreads();

    const int th = tid & 15;
    const int te = tid >> 4;

    u64 acc[4][2];
    {
        float4 bv = __ldg((const float4*)b1 + th);
        u64 p0 = pack_pair(bv.x, bv.y);
        u64 p1 = pack_pair(bv.z, bv.w);
        #pragma unroll
        for (int i = 0; i < 4; i++) { acc[i][0] = p0; acc[i][1] = p1; }
    }
    accum_l1<128, NSTR>(buf, W1, te, th, acc);
    __syncthreads();

    #pragma unroll
    for (int i = 0; i < 4; i++) {
        float2 h0 = unpack(acc[i][0]);
        float2 h1 = unpack(acc[i][1]);
        float4 h;
        h.x = fmaxf(h0.x, 0.f); h.y = fmaxf(h0.y, 0.f);
        h.z = fmaxf(h1.x, 0.f); h.w = fmaxf(h1.y, 0.f);
        *(float4*)(buf + (te * 4 + i) * BSTR + th * 4) = h;
    }
    __syncthreads();

    u64 acc2[4][2];
    {
        float4 bv = __ldg((const float4*)b2 + th);
        u64 p0 = pack_pair(bv.x, bv.y);
        u64 p1 = pack_pair(bv.z, bv.w);
        #pragma unroll
        for (int i = 0; i < 4; i++) { acc2[i][0] = p0; acc2[i][1] = p1; }
    }
    accum_l1<64, BSTR>(buf, W2, te, th, acc2);

    #pragma unroll
    for (int i = 0; i < 4; i++) {
        int gn = n0 + te * 4 + i;
        if (gn < N_NODES) {
            float2 o0 = unpack(acc2[i][0]);
            float2 o1 = unpack(acc2[i][1]);
            float4 ov; ov.x = o0.x; ov.y = o0.y; ov.z = o1.x; ov.w = o1.y;
            *(float4*)(o + (size_t)gn * DN + th * 4) = ov;
        }
    }
}

extern "C" void kernel_launch(void* const* d_in, const int* in_sizes, int n_in,
                              void* d_out, int out_size) {
    const float* x_a  = (const float*)d_in[0];
    const float* x_b  = (const float*)d_in[1];
    const int*   ei_aa = (const int*)d_in[2];
    const int*   ei_ab = (const int*)d_in[3];
    const int*   ei_bb = (const int*)d_in[4];
    const float* ea_aa = (const float*)d_in[5];
    const float* ea_ab = (const float*)d_in[6];
    const float* ea_bb = (const float*)d_in[7];
    const float* We1 = (const float*)d_in[8];
    const float* be1 = (const float*)d_in[9];
    const float* We2 = (const float*)d_in[10];
    const float* be2 = (const float*)d_in[11];
    const float* Wn1 = (const float*)d_in[12];
    const float* bn1 = (const float*)d_in[13];
    const float* Wn2 = (const float*)d_in[14];
    const float* bn2 = (const float*)d_in[15];

    float* out   = (float*)d_out;
    float* nx_a  = out;
    float* ne_base = out + 2 * (size_t)N_NODES * DN;   // ne_aa, ne_ab, ne_bb

    cudaFuncSetAttribute(edge_tc, cudaFuncAttributeMaxDynamicSharedMemorySize, ESMEM);

    zero_kernel<<<1024, 256>>>();

    pre_gemm<<<6 * NB, NT>>>(x_a, x_b, We1, be1);

    edge_tc<<<3 * EB2, 256, ESMEM>>>(ei_aa, ei_ab, ei_bb,
                                     ea_aa, ea_ab, ea_bb,
                                     We1, We2, be2, ne_base);

    node_all<<<2 * NB, NT>>>(x_a, x_b, Wn1, bn1, Wn2, bn2, nx_a);
}

// round 7
// speedup vs baseline: 1.0313x; 1.0313x over previous
#include <cuda_runtime.h>
#include <cuda_bf16.h>
#include <mma.h>
#include <cstdint>

#define N_NODES 100000
#define E_EDGES 400000
#define DN 64
#define DE 32
#define DH 64
#define DIN_E 160
#define DIN_N 128
#define TN 64
#define NT 256
#define NB ((N_NODES + TN - 1) / TN)    // 1563
#define BSTR 68
#define NSTR 132

#define TE2 128
#define EB2 (E_EDGES / TE2)             // 3125 exact

typedef unsigned long long u64;
using namespace nvcuda;

// Scratch (no cudaMalloc allowed).
// slots: 0 = a<-aa(row), 1 = a<-ab(row), 2 = b<-ab(col), 3 = b<-bb(row)
__device__ float g_sum[4][N_NODES * DE];
__device__ float g_cnt[4][N_NODES];
// Precomputed per-node edge-layer1 partials.
// seg: 0=P0(xa,A0,+b) 1=Q0(xa,B0) 2=P1(xa,A1,+b) 3=Q1(xb,B1) 4=P2(xb,A2,+b) 5=Q2(xb,B2)
__device__ float g_PQ[6][N_NODES * DH];

__global__ void zero_kernel() {
    int idx = blockIdx.x * blockDim.x + threadIdx.x;
    int stride = gridDim.x * blockDim.x;
    float* s = &g_sum[0][0];
    for (int i = idx; i < 4 * N_NODES * DE; i += stride) s[i] = 0.0f;
    float* c = &g_cnt[0][0];
    for (int i = idx; i < 4 * N_NODES; i += stride) c[i] = 0.0f;
}

// ---- packed fp32x2 helpers (for fp32 kernels) ----
__device__ __forceinline__ u64 pack_dup(float x) {
    u64 r; asm("mov.b64 %0, {%1, %1};" : "=l"(r) : "r"(__float_as_uint(x))); return r;
}
__device__ __forceinline__ u64 pack_pair(float x, float y) {
    u64 r; asm("mov.b64 %0, {%1, %2};" : "=l"(r) : "r"(__float_as_uint(x)), "r"(__float_as_uint(y))); return r;
}
__device__ __forceinline__ float2 unpack(u64 v) {
    float2 f; asm("mov.b64 {%0, %1}, %2;" : "=f"(f.x), "=f"(f.y) : "l"(v)); return f;
}
__device__ __forceinline__ void fma2(u64& acc, u64 a, u64 b) {
    asm("fma.rn.f32x2 %0, %1, %2, %0;" : "+l"(acc) : "l"(a), "l"(b));
}

template <int KW, int STR>
__device__ __forceinline__ void accum_l1(
    const float* buf, const float* __restrict__ W, int te, int th, u64 acc[4][2])
{
    const float* row = buf + (te * 4) * STR;
    #pragma unroll 4
    for (int k = 0; k < KW; k += 4) {
        float4 a0 = *(const float4*)(row + 0 * STR + k);
        float4 a1 = *(const float4*)(row + 1 * STR + k);
        float4 a2 = *(const float4*)(row + 2 * STR + k);
        float4 a3 = *(const float4*)(row + 3 * STR + k);
        const float* a[4] = {(const float*)&a0, (const float*)&a1,
                             (const float*)&a2, (const float*)&a3};
        #pragma unroll
        for (int kk = 0; kk < 4; kk++) {
            ulonglong2 wp = *((const ulonglong2*)(W + (k + kk) * DH) + th);
            #pragma unroll
            for (int i = 0; i < 4; i++) {
                u64 xx = pack_dup(a[i][kk]);
                fma2(acc[i][0], xx, wp.x);
                fma2(acc[i][1], xx, wp.y);
            }
        }
    }
}

// ---------------------------------------------------------------------------
// Precompute kernel: 6 dense GEMMs  g_PQ[seg] = x @ Wblk (+bias for P segs).
// ---------------------------------------------------------------------------
__global__ void __launch_bounds__(NT, 4) pre_gemm(
    const float* __restrict__ x_a, const float* __restrict__ x_b,
    const float* __restrict__ We1, const float* __restrict__ be1)
{
    __shared__ float buf[TN * BSTR];

    const int tid = threadIdx.x;
    const int seg = blockIdx.x / NB;
    const int rblk = blockIdx.x - seg * NB;
    const int r0 = rblk * TN;

    const int type = seg >> 1;
    const int part = seg & 1;
    const float* x = (seg <= 2) ? x_a : x_b;
    const float* W = We1 + type * DIN_E * DH + part * 64 * DH;
    float* outp = g_PQ[seg];

    for (int it = tid; it < TN * 16; it += NT) {
        int n = it >> 4, c = it & 15;
        int gn = r0 + n; if (gn >= N_NODES) gn = N_NODES - 1;
        *(float4*)(buf + n * BSTR + c * 4) =
            __ldg((const float4*)(x + (size_t)gn * DN) + c);
    }
    __syncthreads();

    const int th = tid & 15;
    const int te = tid >> 4;

    u64 acc[4][2];
    if (part == 0) {
        float4 bv = __ldg((const float4*)(be1 + type * DH) + th);
        u64 p0 = pack_pair(bv.x, bv.y);
        u64 p1 = pack_pair(bv.z, bv.w);
        #pragma unroll
        for (int i = 0; i < 4; i++) { acc[i][0] = p0; acc[i][1] = p1; }
    } else {
        #pragma unroll
        for (int i = 0; i < 4; i++) { acc[i][0] = 0ull; acc[i][1] = 0ull; }
    }

    accum_l1<64, BSTR>(buf, W, te, th, acc);

    #pragma unroll
    for (int i = 0; i < 4; i++) {
        int gn = r0 + te * 4 + i;
        if (gn < N_NODES) {
            float2 o0 = unpack(acc[i][0]);
            float2 o1 = unpack(acc[i][1]);
            float4 ov; ov.x = o0.x; ov.y = o0.y; ov.z = o1.x; ov.w = o1.y;
            *(float4*)(outp + (size_t)gn * DH + th * 4) = ov;
        }
    }
}

// ===========================================================================
// Warp-autonomous wmma edge kernel. 8 warps/block, 16 edges per warp, no
// block-wide sync after the weight stage. 3-term bf16 split for accuracy.
// ===========================================================================

// shared weights (staged once)
#define OB1H 0                       // C hi   [32][72] bf16  (4608 B)
#define OB1L 4608                    // C lo
#define OW2H 9216                    // W2 hi  [64][40] bf16  (5120 B)
#define OW2L 14336                   // W2 lo
#define OIDX 19456                   // src[128], dst[128] (1024 B)
#define OWRP 20480                   // per-warp regions, 6912 B each
#define WRP_SZ 6912
#define ESMEM (OWRP + 8 * WRP_SZ)    // 75776

// per-warp region layout (byte offsets within region)
//  phase A:  Ahi @0 (16x40 bf16 =1280), Alo @1280, D @2560 (16x68 f32 =4352)
//  phase H:  Hhi @0 (16x72 bf16 =2304), Hlo @2304  (overwrites A+D head after
//            register-buffered D read), D2 @4608 (16x36 f32 =2304)
#define W_ALO 1280
#define W_D   2560
#define W_HLO 2304
#define W_D2  4608
#define ASTR  40
#define HSTR  72
#define DSTR  68
#define D2STR 36
#define B1STR 72
#define W2STR 40

// split x,y into bf16x2 hi + bf16x2 lo words
__device__ __forceinline__ void split2(float x, float y, uint32_t& hi, uint32_t& lo) {
    __nv_bfloat162 h2 = __float22bfloat162_rn(make_float2(x, y));
    float2 hb = __bfloat1622float2(h2);
    __nv_bfloat162 l2 = __float22bfloat162_rn(make_float2(x - hb.x, y - hb.y));
    hi = *(uint32_t*)&h2;
    lo = *(uint32_t*)&l2;
}

typedef wmma::fragment<wmma::matrix_a, 16, 16, 16, __nv_bfloat16, wmma::row_major> FragA;
typedef wmma::fragment<wmma::matrix_b, 16, 16, 16, __nv_bfloat16, wmma::row_major> FragB;
typedef wmma::fragment<wmma::accumulator, 16, 16, 16, float> FragC;

__global__ void __launch_bounds__(256, 2) edge_tc(
    const int* __restrict__ ei_aa, const int* __restrict__ ei_ab,
    const int* __restrict__ ei_bb,
    const float* __restrict__ ea_aa, const float* __restrict__ ea_ab,
    const float* __restrict__ ea_bb,
    const float* __restrict__ We1,
    const float* __restrict__ We2, const float* __restrict__ be2,
    float* __restrict__ ne_base)
{
    extern __shared__ __align__(256) char smem[];
    __nv_bfloat16* B1h = (__nv_bfloat16*)(smem + OB1H);
    __nv_bfloat16* B1l = (__nv_bfloat16*)(smem + OB1L);
    __nv_bfloat16* W2h = (__nv_bfloat16*)(smem + OW2H);
    __nv_bfloat16* W2l = (__nv_bfloat16*)(smem + OW2L);
    int* sIdx = (int*)(smem + OIDX);

    const int tid = threadIdx.x;
    const int wid = tid >> 5;
    const int lane = tid & 31;

    char* wrp = smem + OWRP + wid * WRP_SZ;
    __nv_bfloat16* Ahi = (__nv_bfloat16*)(wrp);
    __nv_bfloat16* Alo = (__nv_bfloat16*)(wrp + W_ALO);
    float*         D   = (float*)(wrp + W_D);
    __nv_bfloat16* Hhi = (__nv_bfloat16*)(wrp);
    __nv_bfloat16* Hlo = (__nv_bfloat16*)(wrp + W_HLO);
    float*         D2  = (float*)(wrp + W_D2);

    const int type = blockIdx.x / EB2;
    const int e0 = (blockIdx.x - type * EB2) * TE2;

    const int* ei = (type == 0) ? ei_aa : (type == 1) ? ei_ab : ei_bb;
    const float* ea = (type == 0) ? ea_aa : (type == 1) ? ea_ab : ea_bb;
    const float* C  = We1 + type * DIN_E * DH + 128 * DH;   // [32 x 64] (k x n)
    const float* W2 = We2 + type * DH * DE;                 // [64 x 32] (k x n)
    const float* b2 = be2 + type * DE;
    float* ne = ne_base + (size_t)type * E_EDGES * DE;
    const int slot_row = (type == 0) ? 0 : (type == 1) ? 1 : 3;
    const bool has_col = (type == 1);

    // ---- stage weights + indices (one block-wide sync) ----
    if (tid < 128) sIdx[tid] = __ldg(ei + e0 + tid);
    else sIdx[tid] = __ldg(ei + E_EDGES + e0 + tid - 128);
    for (int i = tid; i < 32 * 64; i += 256) {
        int k = i >> 6, n = i & 63;
        float v = __ldg(C + i);
        __nv_bfloat16 h = __float2bfloat16_rn(v);
        B1h[k * B1STR + n] = h;
        B1l[k * B1STR + n] = __float2bfloat16_rn(v - __bfloat162float(h));
    }
    for (int i = tid; i < 64 * 32; i += 256) {
        int k = i >> 5, n = i & 31;
        float v = __ldg(W2 + i);
        __nv_bfloat16 h = __float2bfloat16_rn(v);
        W2h[k * W2STR + n] = h;
        W2l[k * W2STR + n] = __float2bfloat16_rn(v - __bfloat162float(h));
    }
    __syncthreads();

    // ======== per-warp autonomous pipeline (16 edges/warp) ========
    const int r = lane >> 1;              // row within warp tile (0..15)
    const int erow = wid * 16 + r;        // row within block tile (0..127)
    const int ge = e0 + erow;             // global edge

    // ---- stage A (ea rows, split) ----
    {
        int cb = (lane & 1) * 16;
        const float4* earow = (const float4*)(ea + (size_t)ge * DE + cb);
        #pragma unroll
        for (int g = 0; g < 4; g++) {
            float4 v = __ldg(earow + g);
            uint32_t h0, l0, h1, l1;
            split2(v.x, v.y, h0, l0);
            split2(v.z, v.w, h1, l1);
            int o = r * ASTR + cb + g * 4;
            *(uint2*)(Ahi + o) = make_uint2(h0, h1);
            *(uint2*)(Alo + o) = make_uint2(l0, l1);
        }
    }
    __syncwarp();

    // ---- MMA1: D[16x64] = ea @ C ----
    {
        FragA aH[2], aL[2];
        #pragma unroll
        for (int k = 0; k < 2; k++) {
            wmma::load_matrix_sync(aH[k], Ahi + k * 16, ASTR);
            wmma::load_matrix_sync(aL[k], Alo + k * 16, ASTR);
        }
        #pragma unroll
        for (int nt = 0; nt < 4; nt++) {
            FragC acc;
            wmma::fill_fragment(acc, 0.0f);
            #pragma unroll
            for (int k = 0; k < 2; k++) {
                FragB bH, bL;
                wmma::load_matrix_sync(bH, B1h + k * 16 * B1STR + nt * 16, B1STR);
                wmma::load_matrix_sync(bL, B1l + k * 16 * B1STR + nt * 16, B1STR);
                wmma::mma_sync(acc, aH[k], bH, acc);
                wmma::mma_sync(acc, aH[k], bL, acc);
                wmma::mma_sync(acc, aL[k], bH, acc);
            }
            wmma::store_matrix_sync(D + nt * 16, acc, DSTR, wmma::mem_row_major);
        }
    }
    __syncwarp();

    // ---- epilogue 1: h = relu(D + P[src] + Q[dst]) -> split, buffered in regs ----
    {
        int cb = (lane & 1) * 32;
        int s = sIdx[erow], d = sIdx[128 + erow];
        const float4* Pp = (const float4*)(g_PQ[2 * type] + (size_t)s * DH + cb);
        const float4* Qp = (const float4*)(g_PQ[2 * type + 1] + (size_t)d * DH + cb);
        const float* drow = D + r * DSTR + cb;
        uint2 hiw[8], low[8];
        #pragma unroll
        for (int g = 0; g < 8; g++) {
            float4 p = __ldg(Pp + g);
            float4 q = __ldg(Qp + g);
            float4 dv = *(const float4*)(drow + g * 4);
            float h0 = fmaxf(dv.x + p.x + q.x, 0.f);
            float h1 = fmaxf(dv.y + p.y + q.y, 0.f);
            float h2 = fmaxf(dv.z + p.z + q.z, 0.f);
            float h3 = fmaxf(dv.w + p.w + q.w, 0.f);
            split2(h0, h1, hiw[g].x, low[g].x);
            split2(h2, h3, hiw[g].y, low[g].y);
        }
        __syncwarp();   // all lanes done reading D/A before H overwrites
        #pragma unroll
        for (int g = 0; g < 8; g++) {
            int o = r * HSTR + cb + g * 4;
            *(uint2*)(Hhi + o) = hiw[g];
            *(uint2*)(Hlo + o) = low[g];
        }
    }
    __syncwarp();

    // ---- MMA2: D2[16x32] = h @ W2 ----
    {
        FragA aH[4], aL[4];
        #pragma unroll
        for (int k = 0; k < 4; k++) {
            wmma::load_matrix_sync(aH[k], Hhi + k * 16, HSTR);
            wmma::load_matrix_sync(aL[k], Hlo + k * 16, HSTR);
        }
        #pragma unroll
        for (int nt = 0; nt < 2; nt++) {
            FragC acc;
            wmma::fill_fragment(acc, 0.0f);
            #pragma unroll
            for (int k = 0; k < 4; k++) {
                FragB bH, bL;
                wmma::load_matrix_sync(bH, W2h + k * 16 * W2STR + nt * 16, W2STR);
                wmma::load_matrix_sync(bL, W2l + k * 16 * W2STR + nt * 16, W2STR);
                wmma::mma_sync(acc, aH[k], bH, acc);
                wmma::mma_sync(acc, aH[k], bL, acc);
                wmma::mma_sync(acc, aL[k], bH, acc);
            }
            wmma::store_matrix_sync(D2 + nt * 16, acc, D2STR, wmma::mem_row_major);
        }
    }
    __syncwarp();

    // ---- epilogue 2: ne = D2 + b2, write + scatter atomics ----
    {
        int cb = (lane & 1) * 16;
        int s = sIdx[erow], d = sIdx[128 + erow];
        const float* drow = D2 + r * D2STR + cb;
        float* nerow = ne + (size_t)ge * DE + cb;
        float v[16];
        #pragma unroll
        for (int g = 0; g < 4; g++) {
            float4 bb = __ldg((const float4*)(b2 + cb) + g);
            float4 dv = *(const float4*)(drow + g * 4);
            float4 o;
            o.x = dv.x + bb.x; o.y = dv.y + bb.y;
            o.z = dv.z + bb.z; o.w = dv.w + bb.w;
            *(float4*)(nerow + g * 4) = o;
            v[g * 4 + 0] = o.x; v[g * 4 + 1] = o.y;
            v[g * 4 + 2] = o.z; v[g * 4 + 3] = o.w;
        }
        float* sum_row = g_sum[slot_row] + (size_t)s * DE + cb;
        #pragma unroll
        for (int j = 0; j < 16; j++) atomicAdd(sum_row + j, v[j]);
        if (has_col) {
            float* sum_col = g_sum[2] + (size_t)d * DE + cb;
            #pragma unroll
            for (int j = 0; j < 16; j++) atomicAdd(sum_col + j, v[j]);
        }
        if ((lane & 1) == 0) {
            atomicAdd(g_cnt[slot_row] + s, 1.0f);
            if (has_col) atomicAdd(g_cnt[2] + d, 1.0f);
        }
    }
}

// ---------------------------------------------------------------------------
// Node kernel (both types merged) — fp32 path.
// ---------------------------------------------------------------------------
__global__ void __launch_bounds__(NT, 4) node_all(
    const float* __restrict__ x_a, const float* __restrict__ x_b,
    const float* __restrict__ Wn1, const float* __restrict__ bn1,
    const float* __restrict__ Wn2, const float* __restrict__ bn2,
    float* __restrict__ out)
{
    __shared__ float buf[TN * NSTR];

    const int tid = threadIdx.x;
    const int type = blockIdx.x / NB;
    const int nblk = blockIdx.x - type * NB;
    const int n0 = nblk * TN;

    const float* x = type ? x_b : x_a;
    const float* sum1 = g_sum[type ? 2 : 0];
    const float* cnt1 = g_cnt[type ? 2 : 0];
    const float* sum2 = g_sum[type ? 3 : 1];
    const float* cnt2 = g_cnt[type ? 3 : 1];
    const float* W1 = Wn1 + type * DIN_N * DH;
    const float* b1 = bn1 + type * DH;
    const float* W2 = Wn2 + type * DH * DN;
    const float* b2 = bn2 + type * DN;
    float* o = out + (size_t)type * N_NODES * DN;

    for (int it = tid; it < TN * 32; it += NT) {
        int n = it >> 5, c4 = it & 31;
        int gn = n0 + n;
        float4 v = make_float4(0.f, 0.f, 0.f, 0.f);
        if (gn < N_NODES) {
            if (c4 < 16) {
                v = __ldg((const float4*)(x + (size_t)gn * DN) + c4);
            } else if (c4 < 24) {
                v = *((const float4*)(sum1 + (size_t)gn * DE) + (c4 - 16));
                float rc = 1.0f / fmaxf(cnt1[gn], 1.0f);
                v.x *= rc; v.y *= rc; v.z *= rc; v.w *= rc;
            } else {
                v = *((const float4*)(sum2 + (size_t)gn * DE) + (c4 - 24));
                float rc = 1.0f / fmaxf(cnt2[gn], 1.0f);
                v.x *= rc; v.y *= rc; v.z *= rc; v.w *= rc;
            }
        }
        *(float4*)(buf + n * NSTR + c4 * 4) = v;
    }
    __syncthreads();

    const int th = tid & 15;
    const int te = tid >> 4;

    u64 acc[4][2];
    {
        float4 bv = __ldg((const float4*)b1 + th);
        u64 p0 = pack_pair(bv.x, bv.y);
        u64 p1 = pack_pair(bv.z, bv.w);
        #pragma unroll
        for (int i = 0; i < 4; i++) { acc[i][0] = p0; acc[i][1] = p1; }
    }
    accum_l1<128, NSTR>(buf, W1, te, th, acc);
    __syncthreads();

    #pragma unroll
    for (int i = 0; i < 4; i++) {
        float2 h0 = unpack(acc[i][0]);
        float2 h1 = unpack(acc[i][1]);
        float4 h;
        h.x = fmaxf(h0.x, 0.f); h.y = fmaxf(h0.y, 0.f);
        h.z = fmaxf(h1.x, 0.f); h.w = fmaxf(h1.y, 0.f);
        *(float4*)(buf + (te * 4 + i) * BSTR + th * 4) = h;
    }
    __syncthreads();

    u64 acc2[4][2];
    {
        float4 bv = __ldg((const float4*)b2 + th);
        u64 p0 = pack_pair(bv.x, bv.y);
        u64 p1 = pack_pair(bv.z, bv.w);
        #pragma unroll
        for (int i = 0; i < 4; i++) { acc2[i][0] = p0; acc2[i][1] = p1; }
    }
    accum_l1<64, BSTR>(buf, W2, te, th, acc2);

    #pragma unroll
    for (int i = 0; i < 4; i++) {
        int gn = n0 + te * 4 + i;
        if (gn < N_NODES) {
            float2 o0 = unpack(acc2[i][0]);
            float2 o1 = unpack(acc2[i][1]);
            float4 ov; ov.x = o0.x; ov.y = o0.y; ov.z = o1.x; ov.w = o1.y;
            *(float4*)(o + (size_t)gn * DN + th * 4) = ov;
        }
    }
}

extern "C" void kernel_launch(void* const* d_in, const int* in_sizes, int n_in,
                              void* d_out, int out_size) {
    const float* x_a  = (const float*)d_in[0];
    const float* x_b  = (const float*)d_in[1];
    const int*   ei_aa = (const int*)d_in[2];
    const int*   ei_ab = (const int*)d_in[3];
    const int*   ei_bb = (const int*)d_in[4];
    const float* ea_aa = (const float*)d_in[5];
    const float* ea_ab = (const float*)d_in[6];
    const float* ea_bb = (const float*)d_in[7];
    const float* We1 = (const float*)d_in[8];
    const float* be1 = (const float*)d_in[9];
    const float* We2 = (const float*)d_in[10];
    const float* be2 = (const float*)d_in[11];
    const float* Wn1 = (const float*)d_in[12];
    const float* bn1 = (const float*)d_in[13];
    const float* Wn2 = (const float*)d_in[14];
    const float* bn2 = (const float*)d_in[15];

    float* out   = (float*)d_out;
    float* nx_a  = out;
    float* ne_base = out + 2 * (size_t)N_NODES * DN;   // ne_aa, ne_ab, ne_bb

    cudaFuncSetAttribute(edge_tc, cudaFuncAttributeMaxDynamicSharedMemorySize, ESMEM);

    zero_kernel<<<1024, 256>>>();

    pre_gemm<<<6 * NB, NT>>>(x_a, x_b, We1, be1);

    edge_tc<<<3 * EB2, 256, ESMEM>>>(ei_aa, ei_ab, ei_bb,
                                     ea_aa, ea_ab, ea_bb,
                                     We1, We2, be2, ne_base);

    node_all<<<2 * NB, NT>>>(x_a, x_b, Wn1, bn1, Wn2, bn2, nx_a);
}

// round 8
// speedup vs baseline: 1.4184x; 1.3754x over previous
#include <cuda_runtime.h>

#define N_NODES 100000
#define E_EDGES 400000
#define DN 64
#define DE 32
#define DH 64
#define DIN_E 160
#define DIN_N 128
#define TE 64
#define TN 64
#define NT 256
#define EB (E_EDGES / TE)               // 6250 (exact)
#define NB ((N_NODES + TN - 1) / TN)    // 1563
#define BSTR 68                          // 64 + 4 pad (bank skew)
#define NSTR 132                         // 128 + 4 pad

typedef unsigned long long u64;

// Scratch (no cudaMalloc allowed).
// slots: 0 = a<-aa(row), 1 = a<-ab(row), 2 = b<-ab(col), 3 = b<-bb(row)
__device__ float g_sum[4][N_NODES * DE];
__device__ float g_cnt[4][N_NODES];
// Precomputed per-node edge-layer1 partials.
// seg: 0=P0(xa,A0,+b) 1=Q0(xa,B0) 2=P1(xa,A1,+b) 3=Q1(xb,B1) 4=P2(xb,A2,+b) 5=Q2(xb,B2)
__device__ float g_PQ[6][N_NODES * DH];

// ---- packed fp32x2 helpers (sm_103a) ----
__device__ __forceinline__ u64 pack_dup(float x) {
    u64 r; asm("mov.b64 %0, {%1, %1};" : "=l"(r) : "r"(__float_as_uint(x))); return r;
}
__device__ __forceinline__ u64 pack_pair(float x, float y) {
    u64 r; asm("mov.b64 %0, {%1, %2};" : "=l"(r) : "r"(__float_as_uint(x)), "r"(__float_as_uint(y))); return r;
}
__device__ __forceinline__ float2 unpack(u64 v) {
    float2 f; asm("mov.b64 {%0, %1}, %2;" : "=f"(f.x), "=f"(f.y) : "l"(v)); return f;
}
__device__ __forceinline__ void fma2(u64& acc, u64 a, u64 b) {
    asm("fma.rn.f32x2 %0, %1, %2, %0;" : "+l"(acc) : "l"(a), "l"(b));
}

// Accumulate acc[4r][2 h-pairs] += buf[4 rows x KW] @ W[KW x 64].
template <int KW, int STR>
__device__ __forceinline__ void accum_l1(
    const float* buf, const float* __restrict__ W, int te, int th, u64 acc[4][2])
{
    const float* row = buf + (te * 4) * STR;
    #pragma unroll 4
    for (int k = 0; k < KW; k += 4) {
        float4 a0 = *(const float4*)(row + 0 * STR + k);
        float4 a1 = *(const float4*)(row + 1 * STR + k);
        float4 a2 = *(const float4*)(row + 2 * STR + k);
        float4 a3 = *(const float4*)(row + 3 * STR + k);
        const float* a[4] = {(const float*)&a0, (const float*)&a1,
                             (const float*)&a2, (const float*)&a3};
        #pragma unroll
        for (int kk = 0; kk < 4; kk++) {
            ulonglong2 wp = *((const ulonglong2*)(W + (k + kk) * DH) + th);
            #pragma unroll
            for (int i = 0; i < 4; i++) {
                u64 xx = pack_dup(a[i][kk]);
                fma2(acc[i][0], xx, wp.x);
                fma2(acc[i][1], xx, wp.y);
            }
        }
    }
}

// ---------------------------------------------------------------------------
// pre3: per block, 64 rows of one x matrix; stage tile once, run 3 weight
// blocks sequentially -> 3 g_PQ segments. Also zeroes a slice of g_sum/g_cnt.
// grid = 2 * NB; blockIdx.x / NB selects x_a (0) or x_b (1).
// ---------------------------------------------------------------------------
__global__ void __launch_bounds__(NT, 4) pre3(
    const float* __restrict__ x_a, const float* __restrict__ x_b,
    const float* __restrict__ We1, const float* __restrict__ be1)
{
    __shared__ float buf[TN * BSTR];

    const int tid = threadIdx.x;
    const int which = blockIdx.x / NB;        // 0: x_a, 1: x_b
    const int rblk = blockIdx.x - which * NB;
    const int r0 = rblk * TN;

    // ---- fold-in zeroing of segment scratch (slice per block) ----
    {
        const int nblocks = 2 * NB;
        float4* s4 = (float4*)&g_sum[0][0];
        const int total4 = 4 * N_NODES * DE / 4;          // 3.2M float4
        const int per = (total4 + nblocks - 1) / nblocks; // ~1024
        int base = blockIdx.x * per;
        int end = min(base + per, total4);
        for (int i = base + tid; i < end; i += NT)
            s4[i] = make_float4(0.f, 0.f, 0.f, 0.f);
        float* c = &g_cnt[0][0];
        const int ctot = 4 * N_NODES;
        const int cper = (ctot + nblocks - 1) / nblocks;
        int cbase = blockIdx.x * cper;
        int cend = min(cbase + cper, ctot);
        for (int i = cbase + tid; i < cend; i += NT)
            c[i] = 0.0f;
    }

    const float* x = which ? x_b : x_a;

    // Stage x tile [64 x 64]
    for (int it = tid; it < TN * 16; it += NT) {
        int n = it >> 4, cc = it & 15;
        int gn = r0 + n; if (gn >= N_NODES) gn = N_NODES - 1;
        *(float4*)(buf + n * BSTR + cc * 4) =
            __ldg((const float4*)(x + (size_t)gn * DN) + cc);
    }
    __syncthreads();

    const int th = tid & 15;
    const int te = tid >> 4;

    // 3 segments per x matrix
    #pragma unroll
    for (int j = 0; j < 3; j++) {
        const int seg = which * 3 + j;            // 0..5
        const int type = seg >> 1;
        const int part = seg & 1;                 // 0 = P (+bias), 1 = Q
        const float* W = We1 + type * DIN_E * DH + part * 64 * DH;
        float* outp = g_PQ[seg];

        u64 acc[4][2];
        if (part == 0) {
            float4 bv = __ldg((const float4*)(be1 + type * DH) + th);
            u64 p0 = pack_pair(bv.x, bv.y);
            u64 p1 = pack_pair(bv.z, bv.w);
            #pragma unroll
            for (int i = 0; i < 4; i++) { acc[i][0] = p0; acc[i][1] = p1; }
        } else {
            #pragma unroll
            for (int i = 0; i < 4; i++) { acc[i][0] = 0ull; acc[i][1] = 0ull; }
        }

        accum_l1<64, BSTR>(buf, W, te, th, acc);

        #pragma unroll
        for (int i = 0; i < 4; i++) {
            int gn = r0 + te * 4 + i;
            if (gn < N_NODES) {
                float2 o0 = unpack(acc[i][0]);
                float2 o1 = unpack(acc[i][1]);
                float4 ov; ov.x = o0.x; ov.y = o0.y; ov.z = o1.x; ov.w = o1.y;
                *(float4*)(outp + (size_t)gn * DH + th * 4) = ov;
            }
        }
    }
}

// ---------------------------------------------------------------------------
// Edge kernel (all 3 types merged): per block, 64 edges.
// acc = ea_tile @ C, h = relu(acc + P[src] + Q[dst]), layer 2, write + scatter.
// ---------------------------------------------------------------------------
__global__ void __launch_bounds__(NT, 4) edge_all(
    const int* __restrict__ ei_aa, const int* __restrict__ ei_ab,
    const int* __restrict__ ei_bb,
    const float* __restrict__ ea_aa, const float* __restrict__ ea_ab,
    const float* __restrict__ ea_bb,
    const float* __restrict__ We1,
    const float* __restrict__ We2, const float* __restrict__ be2,
    float* __restrict__ ne_base)
{
    __shared__ float buf[TE * BSTR];   // ea tile then hidden
    __shared__ float sW2[DH * DE];
    __shared__ int sIdxR[TE];
    __shared__ int sIdxC[TE];

    const int tid = threadIdx.x;
    const int type = blockIdx.x / EB;
    const int eblk = blockIdx.x - type * EB;
    const int e0 = eblk * TE;

    const int* ei = (type == 0) ? ei_aa : (type == 1) ? ei_ab : ei_bb;
    const float* ea = (type == 0) ? ea_aa : (type == 1) ? ea_ab : ea_bb;
    const float* C  = We1 + type * DIN_E * DH + 128 * DH;   // [32 x 64]
    const float* W2 = We2 + type * DH * DE;
    const float* b2 = be2 + type * DE;
    const float* P = g_PQ[2 * type];
    const float* Q = g_PQ[2 * type + 1];
    float* ne = ne_base + (size_t)type * E_EDGES * DE;
    const int slot_row = (type == 0) ? 0 : (type == 1) ? 1 : 3;
    const bool has_col = (type == 1);

    for (int i = tid; i < DH * DE / 4; i += NT)
        ((float4*)sW2)[i] = ((const float4*)W2)[i];
    if (tid < TE) sIdxR[tid] = ei[e0 + tid];
    else if (tid < 2 * TE) sIdxC[tid - TE] = ei[E_EDGES + e0 + tid - TE];
    for (int it = tid; it < TE * 8; it += NT) {
        int e = it >> 3, c = it & 7;
        *(float4*)(buf + e * BSTR + c * 4) =
            __ldg((const float4*)(ea + (size_t)(e0 + e) * DE) + c);
    }
    __syncthreads();

    const int th = tid & 15;
    const int te = tid >> 4;

    u64 acc[4][2];
    #pragma unroll
    for (int i = 0; i < 4; i++) { acc[i][0] = 0ull; acc[i][1] = 0ull; }
    accum_l1<32, BSTR>(buf, C, te, th, acc);

    float4 hv[4];
    #pragma unroll
    for (int i = 0; i < 4; i++) {
        int e = te * 4 + i;
        float4 p = __ldg((const float4*)(P + (size_t)sIdxR[e] * DH) + th);
        float4 q = __ldg((const float4*)(Q + (size_t)sIdxC[e] * DH) + th);
        float2 a0 = unpack(acc[i][0]);
        float2 a1 = unpack(acc[i][1]);
        hv[i].x = fmaxf(a0.x + p.x + q.x, 0.f);
        hv[i].y = fmaxf(a0.y + p.y + q.y, 0.f);
        hv[i].z = fmaxf(a1.x + p.z + q.z, 0.f);
        hv[i].w = fmaxf(a1.y + p.w + q.w, 0.f);
    }
    __syncthreads();
    #pragma unroll
    for (int i = 0; i < 4; i++)
        *(float4*)(buf + (te * 4 + i) * BSTR + th * 4) = hv[i];
    __syncthreads();

    u64 acc2[4];
    {
        float2 b2v = __ldg((const float2*)b2 + th);
        u64 p = pack_pair(b2v.x, b2v.y);
        #pragma unroll
        for (int i = 0; i < 4; i++) acc2[i] = p;
    }
    const float* hRow = buf + (te * 4) * BSTR;
    #pragma unroll 4
    for (int k = 0; k < DH; k += 4) {
        float4 a0 = *(const float4*)(hRow + 0 * BSTR + k);
        float4 a1 = *(const float4*)(hRow + 1 * BSTR + k);
        float4 a2 = *(const float4*)(hRow + 2 * BSTR + k);
        float4 a3 = *(const float4*)(hRow + 3 * BSTR + k);
        const float* a[4] = {(const float*)&a0, (const float*)&a1,
                             (const float*)&a2, (const float*)&a3};
        #pragma unroll
        for (int kk = 0; kk < 4; kk++) {
            u64 w = *((const u64*)(sW2 + (k + kk) * DE) + th);
            #pragma unroll
            for (int i = 0; i < 4; i++)
                fma2(acc2[i], pack_dup(a[i][kk]), w);
        }
    }

    float* sum_row = g_sum[slot_row];
    float* cnt_row = g_cnt[slot_row];
    float* sum_col = has_col ? g_sum[2] : nullptr;
    float* cnt_col = has_col ? g_cnt[2] : nullptr;
    #pragma unroll
    for (int i = 0; i < 4; i++) {
        int e = te * 4 + i;
        int ge = e0 + e;
        float2 v = unpack(acc2[i]);
        *(float2*)(ne + (size_t)ge * DE + th * 2) = v;
        int r = sIdxR[e];
        atomicAdd(sum_row + r * DE + th * 2, v.x);
        atomicAdd(sum_row + r * DE + th * 2 + 1, v.y);
        if (has_col) {
            int c = sIdxC[e];
            atomicAdd(sum_col + c * DE + th * 2, v.x);
            atomicAdd(sum_col + c * DE + th * 2 + 1, v.y);
        }
        if (th == 0) {
            atomicAdd(cnt_row + r, 1.0f);
            if (has_col) atomicAdd(cnt_col + sIdxC[e], 1.0f);
        }
    }
}

// ---------------------------------------------------------------------------
// Node kernel (both types merged): per block, 64 nodes.
// ---------------------------------------------------------------------------
__global__ void __launch_bounds__(NT, 4) node_all(
    const float* __restrict__ x_a, const float* __restrict__ x_b,
    const float* __restrict__ Wn1, const float* __restrict__ bn1,
    const float* __restrict__ Wn2, const float* __restrict__ bn2,
    float* __restrict__ out)
{
    __shared__ float buf[TN * NSTR];

    const int tid = threadIdx.x;
    const int type = blockIdx.x / NB;
    const int nblk = blockIdx.x - type * NB;
    const int n0 = nblk * TN;

    const float* x = type ? x_b : x_a;
    const float* sum1 = g_sum[type ? 2 : 0];
    const float* cnt1 = g_cnt[type ? 2 : 0];
    const float* sum2 = g_sum[type ? 3 : 1];
    const float* cnt2 = g_cnt[type ? 3 : 1];
    const float* W1 = Wn1 + type * DIN_N * DH;
    const float* b1 = bn1 + type * DH;
    const float* W2 = Wn2 + type * DH * DN;
    const float* b2 = bn2 + type * DN;
    float* o = out + (size_t)type * N_NODES * DN;

    for (int it = tid; it < TN * 32; it += NT) {
        int n = it >> 5, c4 = it & 31;
        int gn = n0 + n;
        float4 v = make_float4(0.f, 0.f, 0.f, 0.f);
        if (gn < N_NODES) {
            if (c4 < 16) {
                v = __ldg((const float4*)(x + (size_t)gn * DN) + c4);
            } else if (c4 < 24) {
                v = *((const float4*)(sum1 + (size_t)gn * DE) + (c4 - 16));
                float rc = 1.0f / fmaxf(cnt1[gn], 1.0f);
                v.x *= rc; v.y *= rc; v.z *= rc; v.w *= rc;
            } else {
                v = *((const float4*)(sum2 + (size_t)gn * DE) + (c4 - 24));
                float rc = 1.0f / fmaxf(cnt2[gn], 1.0f);
                v.x *= rc; v.y *= rc; v.z *= rc; v.w *= rc;
            }
        }
        *(float4*)(buf + n * NSTR + c4 * 4) = v;
    }
    __syncthreads();

    const int th = tid & 15;
    const int te = tid >> 4;

    u64 acc[4][2];
    {
        float4 bv = __ldg((const float4*)b1 + th);
        u64 p0 = pack_pair(bv.x, bv.y);
        u64 p1 = pack_pair(bv.z, bv.w);
        #pragma unroll
        for (int i = 0; i < 4; i++) { acc[i][0] = p0; acc[i][1] = p1; }
    }
    accum_l1<128, NSTR>(buf, W1, te, th, acc);
    __syncthreads();

    #pragma unroll
    for (int i = 0; i < 4; i++) {
        float2 h0 = unpack(acc[i][0]);
        float2 h1 = unpack(acc[i][1]);
        float4 h;
        h.x = fmaxf(h0.x, 0.f); h.y = fmaxf(h0.y, 0.f);
        h.z = fmaxf(h1.x, 0.f); h.w = fmaxf(h1.y, 0.f);
        *(float4*)(buf + (te * 4 + i) * BSTR + th * 4) = h;
    }
    __syncthreads();

    u64 acc2[4][2];
    {
        float4 bv = __ldg((const float4*)b2 + th);
        u64 p0 = pack_pair(bv.x, bv.y);
        u64 p1 = pack_pair(bv.z, bv.w);
        #pragma unroll
        for (int i = 0; i < 4; i++) { acc2[i][0] = p0; acc2[i][1] = p1; }
    }
    accum_l1<64, BSTR>(buf, W2, te, th, acc2);

    #pragma unroll
    for (int i = 0; i < 4; i++) {
        int gn = n0 + te * 4 + i;
        if (gn < N_NODES) {
            float2 o0 = unpack(acc2[i][0]);
            float2 o1 = unpack(acc2[i][1]);
            float4 ov; ov.x = o0.x; ov.y = o0.y; ov.z = o1.x; ov.w = o1.y;
            *(float4*)(o + (size_t)gn * DN + th * 4) = ov;
        }
    }
}

extern "C" void kernel_launch(void* const* d_in, const int* in_sizes, int n_in,
                              void* d_out, int out_size) {
    const float* x_a  = (const float*)d_in[0];
    const float* x_b  = (const float*)d_in[1];
    const int*   ei_aa = (const int*)d_in[2];
    const int*   ei_ab = (const int*)d_in[3];
    const int*   ei_bb = (const int*)d_in[4];
    const float* ea_aa = (const float*)d_in[5];
    const float* ea_ab = (const float*)d_in[6];
    const float* ea_bb = (const float*)d_in[7];
    const float* We1 = (const float*)d_in[8];
    const float* be1 = (const float*)d_in[9];
    const float* We2 = (const float*)d_in[10];
    const float* be2 = (const float*)d_in[11];
    const float* Wn1 = (const float*)d_in[12];
    const float* bn1 = (const float*)d_in[13];
    const float* Wn2 = (const float*)d_in[14];
    const float* bn2 = (const float*)d_in[15];

    float* out   = (float*)d_out;
    float* nx_a  = out;
    float* ne_base = out + 2 * (size_t)N_NODES * DN;   // ne_aa, ne_ab, ne_bb

    pre3<<<2 * NB, NT>>>(x_a, x_b, We1, be1);

    edge_all<<<3 * EB, NT>>>(ei_aa, ei_ab, ei_bb,
                             ea_aa, ea_ab, ea_bb,
                             We1, We2, be2, ne_base);

    node_all<<<2 * NB, NT>>>(x_a, x_b, Wn1, bn1, Wn2, bn2, nx_a);
}